// round 14
// baseline (speedup 1.0000x reference)
#include <cuda_runtime.h>

// Shapes: x, y : (16, 64, 256, 256) fp32 ; out : (16, 256, 256) fp32
// out[b,i] = sum_c x[b,c,i] * w[b,c],  w[b,c] = sum_j y[b,c,j] / (65536*4194304)
//
// R14 EXPERIMENT: 128-thread blocks (grid unchanged at 1024, same per-batch
// ticket barrier and plane/chunk mapping). launch_bounds(128,7) -> 1036
// resident blocks >= 1024 (barrier-safe) but only 896 threads/SM, giving
// ptxas up to 73 regs/thread (vs the 32-reg cap at 256 threads) -> ~3x more
// in-flight LDG.128 per thread, ~+30% aggregate MLP. Discriminates
// MLP-limited vs HBM-efficiency-limited at the current 6.7 TB/s plateau.
//
// Each thread: 128 y-float4 in phase A; 2 output float4 in phase B.

#define NB 16
#define NC 64
#define HW 65536               // 256*256
#define HW4 (HW / 4)           // 16384 float4 per (b,c) plane
#define SCALE (1.0f / (65536.0f * 4194304.0f))  // exact: 2^-38

__device__ float g_w[NB * NC];
__device__ unsigned int g_cnt[NB];     // monotonic ticket counter (never reset)

__global__ void __launch_bounds__(128, 7)
fused_kernel(const float4* __restrict__ x4,
             const float4* __restrict__ y4,
             float4* __restrict__ out4) {
    const int blk = blockIdx.x;            // 0..1023 == plane index b*64+c
    const int b = blk >> 6;                // batch
    const int own_c = blk & 63;            // this block's channel / output chunk
    const int t = threadIdx.x;             // 0..127

    __shared__ float w[NC];
    __shared__ float red[4];
    __shared__ unsigned int s_target;

    // ---------------- Phase A: reduce y-plane blk ----------------
    {
        const float4* p = y4 + (size_t)blk * HW4;
        float s0 = 0.0f, s1 = 0.0f;
        // 16384 float4 / 128 threads = 128 per thread; two independent
        // accumulator chains, 8 independent addresses per unrolled body.
        #pragma unroll 8
        for (int k = 0; k < 64; ++k) {
            float4 va = __ldcs(&p[t + (2 * k)     * 128]);
            float4 vb = __ldcs(&p[t + (2 * k + 1) * 128]);
            s0 += (va.x + va.y) + (va.z + va.w);
            s1 += (vb.x + vb.y) + (vb.z + vb.w);
        }
        float s = s0 + s1;
        #pragma unroll
        for (int o = 16; o > 0; o >>= 1)
            s += __shfl_xor_sync(0xFFFFFFFF, s, o);
        if ((t & 31) == 0) red[t >> 5] = s;
    }
    __syncthreads();

    // ------------- Publish w_own + barrier ARRIVE (ticket, no wait) --------
    float w_own = 0.0f;
    if (t == 0) {
        float tot = (red[0] + red[1]) + (red[2] + red[3]);
        const float wo = tot * SCALE;
        g_w[blk] = wo;                                // publish for batch peers
        red[0] = wo;                                  // local broadcast slot
        __threadfence();                              // release g_w[blk]
        unsigned ticket = atomicAdd(&g_cnt[b], 1u);   // totally ordered arrive
        s_target = ((ticket >> 6) + 1u) << 6;         // end of this round
    }
    __syncthreads();
    w_own = red[0];

    // ------- Phase B part 1: own plane pre-accumulation (overlaps wait) ----
    // Block's output chunk = 256 float4; each thread owns elements t and t+128.
    const float4* pxb = x4 + (size_t)b * NC * HW4 + own_c * 256 + t;
    float4 a0, a1;
    {
        float4 v0 = __ldcs(pxb + (size_t)own_c * HW4);
        float4 v1 = __ldcs(pxb + (size_t)own_c * HW4 + 128);
        a0.x = v0.x * w_own; a0.y = v0.y * w_own;
        a0.z = v0.z * w_own; a0.w = v0.w * w_own;
        a1.x = v1.x * w_own; a1.y = v1.y * w_own;
        a1.z = v1.z * w_own; a1.w = v1.w * w_own;
    }

    // ---------------- Barrier WAIT (overlapped by the loads above) ---------
    if (t == 0) {
        const unsigned target = s_target;
        while (*(volatile unsigned*)&g_cnt[b] < target)
            __nanosleep(64);
        __threadfence();                              // acquire before g_w reads
    }
    __syncthreads();
    if (t < NC) w[t] = __ldcg(&g_w[b * NC + t]);      // L2-coherent reload
    __syncthreads();

    // ------- Phase B part 2: 63 planes, branch-free index remap ------------
    // c = k + (k >= own_c) visits 0..63 except own_c; 2 independent loads per
    // iteration, addresses independent -> deep front-batching with 73 regs.
    #pragma unroll 7
    for (int k = 0; k < NC - 1; ++k) {
        const int c = k + (int)(k >= own_c);
        float4 v0 = __ldcs(pxb + (size_t)c * HW4);
        float4 v1 = __ldcs(pxb + (size_t)c * HW4 + 128);
        const float wc = w[c];
        a0.x += v0.x * wc; a0.y += v0.y * wc;
        a0.z += v0.z * wc; a0.w += v0.w * wc;
        a1.x += v1.x * wc; a1.y += v1.y * wc;
        a1.z += v1.z * wc; a1.w += v1.w * wc;
    }

    const size_t ob = (size_t)blk * 256 + t;
    out4[ob]       = a0;
    out4[ob + 128] = a1;
}

extern "C" void kernel_launch(void* const* d_in, const int* in_sizes, int n_in,
                              void* d_out, int out_size) {
    const float4* x4 = (const float4*)d_in[0];
    const float4* y4 = (const float4*)d_in[1];
    float4* out4 = (float4*)d_out;

    fused_kernel<<<NB * NC, 128>>>(x4, y4, out4);
}

// round 15
// speedup vs baseline: 1.0250x; 1.0250x over previous
#include <cuda_runtime.h>

// Shapes: x, y : (16, 64, 256, 256) fp32 ; out : (16, 256, 256) fp32
// out[b,i] = sum_c x[b,c,i] * w[b,c],  w[b,c] = sum_j y[b,c,j] / (65536*4194304)
//
// FINAL (exact R10-winner build; R14's 128-thread/72-reg experiment confirmed
// the 6.7 TB/s plateau is the HBM device-efficiency wall, not MLP — varying
// aggregate in-flight loads +/-30% left bandwidth unchanged).
//
// Fused single kernel, 1024 blocks x 256 threads, all resident in one wave
// (launch_bounds(256,7) -> 7 x 148 = 1036 >= 1024 : required, the per-batch
// barrier deadlocks if any block of a batch is non-resident).
//
// Barrier: monotonic per-batch ticket counter (NEVER reset). ticket/64 gives
// the round; wait until counter >= (round+1)*64. Single location, total order
// from atomicAdd, stale reads only under-read -> deadlock-free by construction.
// Counter value differs across graph replays but output does not.
//
// Validated-by-measurement design ledger (kernel-internal deltas):
//  + fusion vs two kernels:                ~ +1.0 us
//  + own-plane pre-accumulation overlapping the barrier wait: ~ +0.6 us
//  + branch-free phase-B sweep:            ~ +0.6 us
//  + 63-iter index-remap (no own-plane re-read, -4MB traffic): ~ +0.6 us
//  - grid=256 "long burst" variant:        -16 us  (occupancy/MLP collapse)
//  - additive pointer stepping:            -1.5 us (serialized address chain)
//  = unroll 9 / 128-thr 72-reg / cache-hint variants: neutral (HBM wall)
//
// Converged: kernel 80.8 +/- 0.7 us @ 6.6-6.8 TB/s (84-85% DRAM) = ~96% of
// the 76.2us floor for the minimal 516MB of traffic at this chip's achieved
// streaming ceiling.

#define NB 16
#define NC 64
#define HW 65536               // 256*256
#define HW4 (HW / 4)           // 16384 float4 per (b,c) plane
#define SCALE (1.0f / (65536.0f * 4194304.0f))  // exact: 2^-38

__device__ float g_w[NB * NC];
__device__ unsigned int g_cnt[NB];     // monotonic ticket counter (never reset)

__global__ void __launch_bounds__(256, 7)
fused_kernel(const float4* __restrict__ x4,
             const float4* __restrict__ y4,
             float4* __restrict__ out4) {
    const int blk = blockIdx.x;            // 0..1023 == plane index b*64+c
    const int b = blk >> 6;                // batch
    const int own_c = blk & 63;            // this block's channel / output chunk
    const int t = threadIdx.x;

    __shared__ float w[NC];
    __shared__ float red[8];
    __shared__ unsigned int s_target;

    // ---------------- Phase A: reduce y-plane blk ----------------
    {
        const float4* p = y4 + (size_t)blk * HW4;
        float s = 0.0f;
        #pragma unroll 8
        for (int k = 0; k < 64; ++k) {
            float4 v = __ldcs(&p[t + k * 256]);   // y read exactly once: stream
            s += (v.x + v.y) + (v.z + v.w);
        }
        #pragma unroll
        for (int o = 16; o > 0; o >>= 1)
            s += __shfl_xor_sync(0xFFFFFFFF, s, o);
        if ((t & 31) == 0) red[t >> 5] = s;
    }
    __syncthreads();

    // ------------- Publish w_own + barrier ARRIVE (ticket, no wait) --------
    float w_own = 0.0f;
    if (t == 0) {
        float tot = 0.0f;
        #pragma unroll
        for (int i = 0; i < 8; ++i) tot += red[i];
        const float wo = tot * SCALE;
        g_w[blk] = wo;                                // publish for batch peers
        red[0] = wo;                                  // local broadcast slot
        __threadfence();                              // release g_w[blk]
        unsigned ticket = atomicAdd(&g_cnt[b], 1u);   // totally ordered arrive
        s_target = ((ticket >> 6) + 1u) << 6;         // end of this round
    }
    __syncthreads();
    w_own = red[0];

    // ------- Phase B part 1: own plane pre-accumulation (overlaps wait) ----
    const float4* pxb = x4 + (size_t)b * NC * HW4 + own_c * 256 + t;
    float4 acc;
    {
        float4 v = __ldcs(pxb + (size_t)own_c * HW4); // own plane read ONCE
        acc.x = v.x * w_own;
        acc.y = v.y * w_own;
        acc.z = v.z * w_own;
        acc.w = v.w * w_own;
    }

    // ---------------- Barrier WAIT (overlapped by the loads above) ---------
    if (t == 0) {
        const unsigned target = s_target;
        while (*(volatile unsigned*)&g_cnt[b] < target)
            __nanosleep(64);
        __threadfence();                              // acquire before g_w reads
    }
    __syncthreads();
    if (t < NC) w[t] = __ldcg(&g_w[b * NC + t]);      // L2-coherent reload
    __syncthreads();

    // ------- Phase B part 2: 63 planes, branch-free index remap ------------
    // c = k + (k >= own_c) visits 0..63 except own_c; per-iteration cost is
    // one ISETP+IADD (ALU ~7% busy), addresses independent -> batching kept.
    #pragma unroll 7
    for (int k = 0; k < NC - 1; ++k) {
        const int c = k + (int)(k >= own_c);
        float4 v = __ldcs(pxb + (size_t)c * HW4);     // x read exactly once
        const float wc = w[c];
        acc.x += v.x * wc;
        acc.y += v.y * wc;
        acc.z += v.z * wc;
        acc.w += v.w * wc;
    }

    out4[(size_t)blk * 256 + t] = acc;
}

extern "C" void kernel_launch(void* const* d_in, const int* in_sizes, int n_in,
                              void* d_out, int out_size) {
    const float4* x4 = (const float4*)d_in[0];
    const float4* y4 = (const float4*)d_in[1];
    float4* out4 = (float4*)d_out;

    fused_kernel<<<NB * NC, 256>>>(x4, y4, out4);
}